// round 3
// baseline (speedup 1.0000x reference)
#include <cuda_runtime.h>

// labels[c] = argmax_q code_book[c][q]  (first-occurrence tie-break)
//   == reference argmin_q (tn[b,l,c] - cbn[c,q]): tn is constant over q and
//   cbn is a monotone strictly-increasing affine map of code_book, so the
//   GEMM + both LayerNorms + the (B,L,C,Q) distance tensor are dead code.
// Every output row (B*L = 2048 of them) is an identical copy of labels[0..255]
// stored as float32.  Fused single kernel: each block redundantly computes all
// 256 labels (256 KB L2-hot read), then writes its 64-row slice of the output.

static constexpr int C     = 256;
static constexpr int Qdim  = 256;
static constexpr int BLOCKS  = 32;
static constexpr int THREADS = 1024;

__global__ void __launch_bounds__(THREADS, 1)
fused_rpq_kernel(const float* __restrict__ cb, float4* __restrict__ out, int n4) {
    __shared__ __align__(16) float labels[C];

    const int tid  = threadIdx.x;
    const int lane = tid & 31;
    const int warp = tid >> 5;

    // ---- Phase 1: per-row argmax, 4 lanes per row, all 256 rows per block ----
    {
        const int row  = warp * 8 + (lane >> 2);   // 0..255
        const int part = lane & 3;                 // quarter-row: 64 floats
        const float4* __restrict__ rp =
            reinterpret_cast<const float4*>(cb + row * Qdim + part * 64);

        // packed key: (sortable_float_bits << 32) | (255 - q)
        // max() => max value; among exact ties => min q (matches jnp first-index)
        unsigned long long best = 0ull;
#pragma unroll
        for (int i = 0; i < 16; ++i) {
            const float4 v = __ldg(rp + i);
            const int qb = part * 64 + i * 4;
            const float vs[4] = {v.x, v.y, v.z, v.w};
#pragma unroll
            for (int j = 0; j < 4; ++j) {
                const unsigned u   = __float_as_uint(vs[j]);
                const unsigned key = u ^ (unsigned)(((int)u >> 31) | 0x80000000);
                const unsigned long long p =
                    ((unsigned long long)key << 32) | (unsigned)(255 - (qb + j));
                if (p > best) best = p;
            }
        }
        // reduce across the 4 collaborating lanes
#pragma unroll
        for (int off = 1; off <= 2; off <<= 1) {
            const unsigned long long o = __shfl_xor_sync(0xffffffffu, best, off);
            if (o > best) best = o;
        }
        if (part == 0)
            labels[row] = (float)(255 - (int)(best & 0xFFu));
    }
    __syncthreads();

    // ---- Phase 2: write 64 output rows per block (4096 float4) ----
    // slot indices tid + i*1024 are congruent mod 64 => one shared read serves
    // all four stores.
    const float4* __restrict__ lab4 = reinterpret_cast<const float4*>(labels);
    const float4 v = lab4[tid & 63];
    const int base = blockIdx.x * 4096;
#pragma unroll
    for (int i = 0; i < 4; ++i) {
        const int idx = base + tid + i * 1024;
        if (idx < n4) out[idx] = v;
    }
}

extern "C" void kernel_launch(void* const* d_in, const int* in_sizes, int n_in,
                              void* d_out, int out_size) {
    // Locate code_book by element count (65536); sizes are all distinct.
    const float* code_book = nullptr;
    for (int i = 0; i < n_in; ++i) {
        if (in_sizes[i] == C * Qdim) { code_book = (const float*)d_in[i]; break; }
    }
    if (!code_book) code_book = (const float*)d_in[2];

    const int n4 = out_size / 4;   // 131072 float4 == BLOCKS * 4096
    fused_rpq_kernel<<<BLOCKS, THREADS>>>(code_book,
                                          reinterpret_cast<float4*>(d_out), n4);
}

// round 4
// speedup vs baseline: 2.1907x; 2.1907x over previous
#include <cuda_runtime.h>

// labels[c] = argmax_q code_book[c][q]  (first-occurrence tie-break)
//   == reference argmin_q (tn[b,l,c] - cbn[c,q]): tn is constant over q and
//   cbn is a monotone strictly-increasing affine map of code_book, so the
//   GEMM, both LayerNorms, and the (B,L,C,Q) distance tensor are dead code.
// Output (B,L,C)=(4,512,256) f32: every row = labels[0..255].
//
// Single fused kernel, zero redundancy, zero inter-block dependency:
// block (cg, rg) computes labels for codebook rows [8cg, 8cg+8) and writes
// that 8-column slice for output rows [256rg, 256rg+256).

static constexpr int C    = 256;
static constexpr int Qdim = 256;

__global__ void __launch_bounds__(256, 8)
fused_rpq_kernel(const float* __restrict__ cb, float4* __restrict__ out) {
    __shared__ __align__(16) float lab[8];

    const int tid  = threadIdx.x;
    const int lane = tid & 31;
    const int warp = tid >> 5;
    const int cg   = blockIdx.x & 31;   // column group: codebook rows [8cg, 8cg+8)
    const int rg   = blockIdx.x >> 5;   // row group: output rows [256rg, 256rg+256)

    // ---- Phase 1: warp w -> argmax of codebook row 8cg+w ----
    {
        const int row = cg * 8 + warp;
        const float4* __restrict__ rp =
            reinterpret_cast<const float4*>(cb + row * Qdim) + lane * 2;
        const float4 a = __ldg(rp);
        const float4 b = __ldg(rp + 1);

        // per-lane best over q = 8*lane .. 8*lane+7 (strict > keeps first index)
        float bv = a.x; int bi = 0;
        if (a.y > bv) { bv = a.y; bi = 1; }
        if (a.z > bv) { bv = a.z; bi = 2; }
        if (a.w > bv) { bv = a.w; bi = 3; }
        if (b.x > bv) { bv = b.x; bi = 4; }
        if (b.y > bv) { bv = b.y; bi = 5; }
        if (b.z > bv) { bv = b.z; bi = 6; }
        if (b.w > bv) { bv = b.w; bi = 7; }
        bi += lane * 8;

#pragma unroll
        for (int off = 16; off; off >>= 1) {
            const float ov = __shfl_down_sync(0xffffffffu, bv, off);
            const int   oi = __shfl_down_sync(0xffffffffu, bi, off);
            if (ov > bv || (ov == bv && oi < bi)) { bv = ov; bi = oi; }
        }
        if (lane == 0) lab[warp] = (float)bi;
    }
    __syncthreads();

    // ---- Phase 2: thread t writes output row 256rg+t, cols [8cg, 8cg+8) ----
    // = two adjacent float4 stores (one aligned 32B sector per row).
    const float4* __restrict__ lab4 = reinterpret_cast<const float4*>(lab);
    const float4 v0 = lab4[0];
    const float4 v1 = lab4[1];
    const int idx = (rg * 256 + tid) * (C / 4) + cg * 2;  // float4 index
    out[idx]     = v0;
    out[idx + 1] = v1;
}

extern "C" void kernel_launch(void* const* d_in, const int* in_sizes, int n_in,
                              void* d_out, int out_size) {
    // Locate code_book by element count (65536); all four sizes are distinct.
    const float* code_book = nullptr;
    for (int i = 0; i < n_in; ++i) {
        if (in_sizes[i] == C * Qdim) { code_book = (const float*)d_in[i]; break; }
    }
    if (!code_book) code_book = (const float*)d_in[2];

    (void)out_size;  // 524288 floats = 2048 rows x 256 cols, covered exactly
    fused_rpq_kernel<<<256, 256>>>(code_book, reinterpret_cast<float4*>(d_out));
}